// round 16
// baseline (speedup 1.0000x reference)
#include <cuda_runtime.h>
#include <cuda_bf16.h>
#include <cuda_fp16.h>
#include <cstdint>

#define B_   8
#define V_   256
#define T_   64

// ---------------------------------------------------------------------------
// Global scratch
// ---------------------------------------------------------------------------
__device__ __half g_xh[8ll * 256 * 64 * 256];            // [b][v][t][256ic] fp16
__device__ __half g_qkv[8ll * 64 * 256 * 192];           // [b][t][v][192] fp16
__device__ __half g_avh[8ll * 256 * 64 * 128];           // [b][v][t][128ic] fp16
__device__ __half g_w1h[192 * 2304];                     // [oc][chunk32][tap][32] fp16
__device__ __half g_w2h[256 * 1152];

// ---------------------------------------------------------------------------
// Helpers
// ---------------------------------------------------------------------------
__device__ __forceinline__ uint32_t smem_u32(const void* p) {
    return (uint32_t)__cvta_generic_to_shared(p);
}
__device__ __forceinline__ uint32_t pack2h(float f0, float f1) {
    __half2 h = __floats2half2_rn(f0, f1);
    return *(uint32_t*)&h;
}

#define LDMX4(r, a) \
    asm volatile("ldmatrix.sync.aligned.m8n8.x4.shared.b16 {%0,%1,%2,%3},[%4];" \
        : "=r"((r)[0]), "=r"((r)[1]), "=r"((r)[2]), "=r"((r)[3]) : "r"(a))
#define LDMX4T(r, a) \
    asm volatile("ldmatrix.sync.aligned.m8n8.x4.trans.shared.b16 {%0,%1,%2,%3},[%4];" \
        : "=r"((r)[0]), "=r"((r)[1]), "=r"((r)[2]), "=r"((r)[3]) : "r"(a))
#define CP16(dst, src, sz) \
    asm volatile("cp.async.cg.shared.global [%0], [%1], 16, %2;" \
                 :: "r"(dst), "l"(src), "r"(sz) : "memory")
#define CP_COMMIT() asm volatile("cp.async.commit_group;" ::: "memory")
#define CP_WAIT(n)  asm volatile("cp.async.wait_group %0;" :: "n"(n) : "memory")

__device__ __forceinline__ void mma16816h(float* c, const uint32_t* a, const uint32_t* b) {
    asm volatile(
        "mma.sync.aligned.m16n8k16.row.col.f32.f16.f16.f32 "
        "{%0,%1,%2,%3},{%4,%5,%6,%7},{%8,%9},{%0,%1,%2,%3};"
        : "+f"(c[0]), "+f"(c[1]), "+f"(c[2]), "+f"(c[3])
        : "r"(a[0]), "r"(a[1]), "r"(a[2]), "r"(a[3]), "r"(b[0]), "r"(b[1]));
}

// ---------------------------------------------------------------------------
// Merged prep kernel:
//   blocks [0, 2048):        split_x   (x NCHW fp32 -> [b][y][t][256ic] fp16)
//   blocks [2048, 3776):     pack_w1   ([oc][ic][3][3] -> [oc][chunk32][tap][32])
//   blocks [3776, 4928):     pack_w2
// ---------------------------------------------------------------------------
__global__ void prep_k(const float* __restrict__ x,
                       const float* __restrict__ wq,
                       const float* __restrict__ wk,
                       const float* __restrict__ wv,
                       const float* __restrict__ wo,
                       __half* __restrict__ xh,
                       __half* __restrict__ w1h,
                       __half* __restrict__ w2h) {
    const int bid = blockIdx.x, tid = threadIdx.x;
    if (bid < 2048) {
        extern __shared__ float s[];               // [256 ic][65]
        const int y = bid & 255, b = bid >> 8;
        for (int r = 0; r < 64; r++) {
            int idx = r * 256 + tid, ic = idx >> 6, t = idx & 63;
            s[ic * 65 + t] = x[(((size_t)b * 256 + ic) * 256 + y) * 64 + t];
        }
        __syncthreads();
        size_t ob = ((size_t)(b * 256 + y)) * 64 * 256;
        for (int r = 0; r < 32; r++) {
            int idx = r * 512 + tid * 2, t = idx >> 8, ic = idx & 255;
            *(uint32_t*)(xh + ob + (size_t)t * 256 + ic)
                = pack2h(s[ic * 65 + t], s[(ic + 1) * 65 + t]);
        }
    } else if (bid < 3776) {
        int id = (bid - 2048) * 256 + tid;          // 192*2304
        int oc = id / 2304, kp = id % 2304;
        int chunk = kp / 288, rem = kp % 288, tap = rem / 32, i = rem & 31;
        int ic = chunk * 32 + i;
        float v;
        if (oc < 32)       v = wq[(oc * 256 + ic) * 9 + tap];
        else if (oc < 64)  v = wk[((oc - 32) * 256 + ic) * 9 + tap];
        else               v = wv[((oc - 64) * 256 + ic) * 9 + tap];
        w1h[id] = __float2half_rn(v);
    } else {
        int id = (bid - 3776) * 256 + tid;          // 256*1152
        int oc = id / 1152, kp = id % 1152;
        int chunk = kp / 288, rem = kp % 288, tap = rem / 32, i = rem & 31;
        int ic = chunk * 32 + i;
        w2h[id] = __float2half_rn(wo[(oc * 128 + ic) * 9 + tap]);
    }
}

// ---------------------------------------------------------------------------
// conv3x3 via mma.sync fp16, single-pass, 32-ic chunks.
// CTA: 256 thr (8 warps: 4 m x 2 n), 2 CTAs/SM. M=256 positions x N=64 oc.
// A double-buffered, B single-buffered (cp.async).
// Patch: [6 rows][66 cols] pixels of 80B stride. B: [64 oc][592B stride].
// Epilogue stages the 256x64 output tile through smem for fully-coalesced
// float4/uint4 global stores (and float4 residual loads).
// ---------------------------------------------------------------------------
#define ABUF    31680          // one A buffer (6*66*80)
#define BH_O    63360          // B base (2*ABUF)
#define CONV_SMEM 101248       // BH_O + 64*592

template<int ICC, int OCTOT, bool TRANS>
__global__ __launch_bounds__(256, 2)
void conv_mma(const __half* __restrict__ inh,
              const __half* __restrict__ wh,
              __half* __restrict__ outh,
              float* __restrict__ out32,
              const float* __restrict__ resid,
              const float* __restrict__ sigma) {
    constexpr int IC = ICC * 32;
    extern __shared__ char sm[];

    const int tid  = threadIdx.x;
    const int lane = tid & 31;
    const int w    = tid >> 5;
    const int ocB  = blockIdx.x * 64;
    const int y0   = blockIdx.y * 4;
    const int b    = blockIdx.z;
    const int m0   = (w & 3) * 64;
    const int n0   = (w >> 2) * 32;
    const uint32_t su = smem_u32(sm);

    float acc[4][4][4];
#pragma unroll
    for (int i = 0; i < 4; i++)
#pragma unroll
        for (int j = 0; j < 4; j++)
#pragma unroll
            for (int e = 0; e < 4; e++) acc[i][j][e] = 0.f;

    auto stageA = [&](int c, int buf) {
        uint32_t au = su + buf * ABUF;
        for (int p = tid; p < 396; p += 256) {
            int row = p / 66, col = p - row * 66;
            int gy = y0 + row - 1, gt = col - 1;
            bool ok = ((unsigned)gy < 256u) && ((unsigned)gt < 64u);
            const __half* src = ok
                ? inh + ((size_t)((b * 256 + gy) * 64 + gt)) * IC + c * 32
                : inh;
            uint32_t dst = au + (uint32_t)p * 80;
            int sz = ok ? 16 : 0;
            CP16(dst,      src,      sz);
            CP16(dst + 16, src + 8,  sz);
            CP16(dst + 32, src + 16, sz);
            CP16(dst + 48, src + 24, sz);
        }
    };
    auto stageB = [&](int c) {
        for (int i = tid; i < 2304; i += 256) {
            int n = i / 36, seg = i - n * 36;
            const __half* src = wh + ((size_t)(ocB + n) * ICC + c) * 288 + seg * 8;
            uint32_t dst = su + BH_O + n * 592 + seg * 16;
            CP16(dst, src, 16);
        }
    };

    stageA(0, 0);
    CP_COMMIT();

    const int l16 = lane & 15;
    const int bg   = lane >> 3;
    const int brow = (bg >> 1) * 8 + (lane & 7);
    const int bko  = (bg & 1) * 16;

    for (int c = 0; c < ICC; ++c) {
        stageB(c);
        CP_COMMIT();
        if (c + 1 < ICC) {
            stageA(c + 1, (c + 1) & 1);
            CP_COMMIT();
            CP_WAIT(1);        // B(c)+A(c) done; A(c+1) in flight
        } else {
            CP_WAIT(0);
        }
        __syncthreads();

        const uint32_t sa = su + (c & 1) * ABUF;
        const uint32_t sb = su + BH_O;
#pragma unroll
        for (int tap = 0; tap < 9; ++tap) {
            const int ky = tap / 3, kx = tap - ky * 3;
#pragma unroll
            for (int kk = 0; kk < 2; ++kk) {
                uint32_t bf0[4], bf1[4];
                {
                    uint32_t ad = sb + (n0 + brow) * 592 + tap * 64 + kk * 32 + bko;
                    LDMX4(bf0, ad);
                    LDMX4(bf1, ad + 16 * 592);
                }
#pragma unroll
                for (int mp = 0; mp < 2; ++mp) {
                    uint32_t a0h[4], a1h[4];
                    {
                        int mrow = m0 + (2 * mp) * 16 + l16;
                        int rp = (mrow >> 6) + ky, cp = (mrow & 63) + kx;
                        uint32_t ad = sa + (uint32_t)(rp * 66 + cp) * 80
                                    + (lane >> 4) * 16 + kk * 32;
                        LDMX4(a0h, ad);
                    }
                    {
                        int mrow = m0 + (2 * mp + 1) * 16 + l16;
                        int rp = (mrow >> 6) + ky, cp = (mrow & 63) + kx;
                        uint32_t ad = sa + (uint32_t)(rp * 66 + cp) * 80
                                    + (lane >> 4) * 16 + kk * 32;
                        LDMX4(a1h, ad);
                    }
                    mma16816h(acc[2 * mp][0],     a0h, &bf0[0]);
                    mma16816h(acc[2 * mp][1],     a0h, &bf0[2]);
                    mma16816h(acc[2 * mp][2],     a0h, &bf1[0]);
                    mma16816h(acc[2 * mp][3],     a0h, &bf1[2]);
                    mma16816h(acc[2 * mp + 1][0], a1h, &bf0[0]);
                    mma16816h(acc[2 * mp + 1][1], a1h, &bf0[2]);
                    mma16816h(acc[2 * mp + 1][2], a1h, &bf1[0]);
                    mma16816h(acc[2 * mp + 1][3], a1h, &bf1[2]);
                }
            }
        }
        __syncthreads();       // protect B buffer + A buffer reuse
    }

    // ---- epilogue: stage tile [256 pos][64 oc] through smem, coalesced out ----
    const int r0l = lane >> 2, c0l = (lane & 3) * 2;
    if constexpr (TRANS) {
        // fp16-pair tile: [pos][34] uint32 (stride 34, payload 32)
        uint32_t* so = (uint32_t*)sm;
#pragma unroll
        for (int mt = 0; mt < 4; ++mt)
#pragma unroll
            for (int nt = 0; nt < 4; ++nt)
#pragma unroll
                for (int h = 0; h < 2; ++h) {
                    int m = m0 + mt * 16 + r0l + h * 8;
                    int oc2 = (n0 + nt * 8 + c0l) >> 1;
                    so[m * 34 + oc2]
                        = pack2h(acc[mt][nt][h * 2], acc[mt][nt][h * 2 + 1]);
                }
        __syncthreads();
#pragma unroll
        for (int j = 0; j < 8; ++j) {
            int idx = j * 256 + tid;
            int pos = idx >> 3, seg = idx & 7;
            int v = y0 + (pos >> 6), t = pos & 63;
            uint32_t r0 = so[pos * 34 + seg * 4 + 0];
            uint32_t r1 = so[pos * 34 + seg * 4 + 1];
            uint32_t r2 = so[pos * 34 + seg * 4 + 2];
            uint32_t r3 = so[pos * 34 + seg * 4 + 3];
            size_t ad = ((size_t)((b * 64 + t) * 256 + v)) * OCTOT + ocB + seg * 8;
            *(uint4*)(outh + ad) = make_uint4(r0, r1, r2, r3);
        }
    } else {
        // fp32 tile: [pos][67] floats (stride 67, payload 64)
        float* so = (float*)sm;
#pragma unroll
        for (int mt = 0; mt < 4; ++mt)
#pragma unroll
            for (int nt = 0; nt < 4; ++nt)
#pragma unroll
                for (int h = 0; h < 2; ++h) {
                    int m = m0 + mt * 16 + r0l + h * 8;
                    int oc = n0 + nt * 8 + c0l;
                    so[m * 67 + oc]     = acc[mt][nt][h * 2];
                    so[m * 67 + oc + 1] = acc[mt][nt][h * 2 + 1];
                }
        __syncthreads();
        float sg = sigma[0];
#pragma unroll
        for (int j = 0; j < 16; ++j) {
            int idx = j * 256 + tid;
            int ocl = idx >> 6;                  // 0..63
            int mb  = (idx & 63) * 4;            // position base 0..252
            size_t ad = ((size_t)(b * OCTOT + ocB + ocl)) * 16384
                      + (size_t)y0 * 64 + mb;
            float4 r = *(const float4*)&resid[ad];
            float4 val;
            val.x = r.x + sg * so[(mb + 0) * 67 + ocl];
            val.y = r.y + sg * so[(mb + 1) * 67 + ocl];
            val.z = r.z + sg * so[(mb + 2) * 67 + ocl];
            val.w = r.w + sg * so[(mb + 3) * 67 + ocl];
            *(float4*)&out32[ad] = val;
        }
    }
}

// ---------------------------------------------------------------------------
// Attention, all-fp16 single-pass mma (flash-style online softmax, fp32 accum).
// One CTA per (b,t,qhalf): 256 thr (8 warps), warp owns 16 of 128 query rows.
// 2 CTAs/SM (regs 256x128=32K, smem 98KB).  K/V loaded fully per CTA.
// SMEM: Q [128 x 80B], K [256 x 80B], V [256 x 272B]  (fp16).
// ---------------------------------------------------------------------------
#define QH_O 0
#define KH_O 10240
#define VH_O 30720
#define ATTN_SMEM 100352

__global__ __launch_bounds__(256, 2)
void attn_kernel(const __half* __restrict__ qkv,
                 __half* __restrict__ avh) {
    extern __shared__ char smc[];
    const int tid  = threadIdx.x;
    const int lane = tid & 31;
    const int w    = tid >> 5;
    const int t    = blockIdx.x;
    const int b    = blockIdx.y;
    const int half = blockIdx.z;
    const uint32_t su = smem_u32(smc);

    const size_t sbase = ((size_t)(b * 64 + t)) * 256 * 192;
    // K + V: all 256 rows, segs 4..23  (5120 float4)
    for (int idx = tid; idx < 5120; idx += 256) {
        int row = idx / 20, seg = idx % 20 + 4;
        float4 val = *(const float4*)(qkv + sbase + (size_t)row * 192 + seg * 8);
        uint32_t dst;
        if (seg < 8)  dst = KH_O + row * 80 + (seg - 4) * 16;
        else          dst = VH_O + row * 272 + (seg - 8) * 16;
        *(float4*)(smc + dst) = val;
    }
    // Q: this CTA's 128 rows, segs 0..3 (512 float4)
    for (int idx = tid; idx < 512; idx += 256) {
        int rl = idx >> 2, seg = idx & 3;
        int row = half * 128 + rl;
        float4 val = *(const float4*)(qkv + sbase + (size_t)row * 192 + seg * 8);
        *(float4*)(smc + QH_O + rl * 80 + seg * 16) = val;
    }
    __syncthreads();

    const int q0  = w * 16;                 // local query base within half
    const int l16 = lane & 15;

    float o[16][4];
#pragma unroll
    for (int i = 0; i < 16; i++)
#pragma unroll
        for (int j = 0; j < 4; j++) o[i][j] = 0.f;
    float mrow[2] = {-1e30f, -1e30f};
    float lrow[2] = {0.f, 0.f};

    for (int c0 = 0; c0 < 4; ++c0) {
        float s[8][4];
#pragma unroll
        for (int i = 0; i < 8; i++)
#pragma unroll
            for (int j = 0; j < 4; j++) s[i][j] = 0.f;

#pragma unroll
        for (int kk = 0; kk < 2; ++kk) {
            uint32_t aH[4];
            uint32_t qa = su + QH_O + (q0 + l16) * 80 + (lane >> 4) * 16 + kk * 32;
            LDMX4(aH, qa);
#pragma unroll
            for (int np = 0; np < 2; ++np) {
                uint32_t kh0[4], kh1[4];
                uint32_t ka0 = su + KH_O + (c0 * 64 + (2 * np) * 16 + l16) * 80
                             + (lane >> 4) * 16 + kk * 32;
                LDMX4(kh0, ka0);
                LDMX4(kh1, ka0 + 16 * 80);
                uint32_t b0h[2] = {kh0[0], kh0[2]}, b1h[2] = {kh0[1], kh0[3]};
                uint32_t b2h[2] = {kh1[0], kh1[2]}, b3h[2] = {kh1[1], kh1[3]};
                mma16816h(s[4 * np],     aH, b0h);
                mma16816h(s[4 * np + 1], aH, b1h);
                mma16816h(s[4 * np + 2], aH, b2h);
                mma16816h(s[4 * np + 3], aH, b3h);
            }
        }

#pragma unroll
        for (int h = 0; h < 2; ++h) {
            float mc = -1e30f;
#pragma unroll
            for (int nt = 0; nt < 8; ++nt)
                mc = fmaxf(mc, fmaxf(s[nt][2 * h], s[nt][2 * h + 1]));
            mc = fmaxf(mc, __shfl_xor_sync(0xffffffffu, mc, 1));
            mc = fmaxf(mc, __shfl_xor_sync(0xffffffffu, mc, 2));
            float mn = fmaxf(mrow[h], mc);
            float sc = __expf(mrow[h] - mn);
            mrow[h] = mn;
            float ls = 0.f;
#pragma unroll
            for (int nt = 0; nt < 8; ++nt) {
                float p0 = __expf(s[nt][2 * h] - mn);
                float p1 = __expf(s[nt][2 * h + 1] - mn);
                s[nt][2 * h] = p0; s[nt][2 * h + 1] = p1;
                ls += p0 + p1;
            }
            ls += __shfl_xor_sync(0xffffffffu, ls, 1);
            ls += __shfl_xor_sync(0xffffffffu, ls, 2);
            lrow[h] = lrow[h] * sc + ls;
#pragma unroll
            for (int nt = 0; nt < 16; ++nt) {
                o[nt][2 * h]     *= sc;
                o[nt][2 * h + 1] *= sc;
            }
        }

#pragma unroll
        for (int kk = 0; kk < 4; ++kk) {
            uint32_t ph[4];
            ph[0] = pack2h(s[2 * kk][0],     s[2 * kk][1]);
            ph[1] = pack2h(s[2 * kk][2],     s[2 * kk][3]);
            ph[2] = pack2h(s[2 * kk + 1][0], s[2 * kk + 1][1]);
            ph[3] = pack2h(s[2 * kk + 1][2], s[2 * kk + 1][3]);
#pragma unroll
            for (int np = 0; np < 4; ++np) {
                uint32_t vh0[4], vh1[4];
                uint32_t va = su + VH_O + (c0 * 64 + kk * 16 + l16) * 272
                            + (lane >> 4) * 16 + (2 * np) * 32;
                LDMX4T(vh0, va);
                LDMX4T(vh1, va + 32);
                uint32_t bh0[2] = {vh0[0], vh0[1]}, bh1[2] = {vh0[2], vh0[3]};
                uint32_t bh2[2] = {vh1[0], vh1[1]}, bh3[2] = {vh1[2], vh1[3]};
                mma16816h(o[4 * np],     ph, bh0);
                mma16816h(o[4 * np + 1], ph, bh1);
                mma16816h(o[4 * np + 2], ph, bh2);
                mma16816h(o[4 * np + 3], ph, bh3);
            }
        }
    }

    float rin[2] = {1.f / lrow[0], 1.f / lrow[1]};
#pragma unroll
    for (int nt = 0; nt < 16; ++nt) {
        int ch = nt * 8 + (lane & 3) * 2;
#pragma unroll
        for (int h = 0; h < 2; ++h) {
            int v = half * 128 + q0 + (lane >> 2) + h * 8;
            size_t ad = ((size_t)(b * 256 + v) * 64 + t) * 128 + ch;
            *(uint32_t*)(avh + ad)
                = pack2h(o[nt][2 * h] * rin[h], o[nt][2 * h + 1] * rin[h]);
        }
    }
}

// ---------------------------------------------------------------------------
extern "C" void kernel_launch(void* const* d_in, const int* in_sizes, int n_in,
                              void* d_out, int out_size) {
    const float* x     = (const float*)d_in[0];
    const float* wq    = (const float*)d_in[1];
    const float* wk    = (const float*)d_in[2];
    const float* wv    = (const float*)d_in[3];
    const float* wo    = (const float*)d_in[4];
    const float* sigma = (const float*)d_in[5];
    float* out = (float*)d_out;

    __half *xh, *qkv, *avh, *w1h, *w2h;
    cudaGetSymbolAddress((void**)&xh,   g_xh);
    cudaGetSymbolAddress((void**)&qkv,  g_qkv);
    cudaGetSymbolAddress((void**)&avh,  g_avh);
    cudaGetSymbolAddress((void**)&w1h,  g_w1h);
    cudaGetSymbolAddress((void**)&w2h,  g_w2h);

    cudaFuncSetAttribute(prep_k,
                         cudaFuncAttributeMaxDynamicSharedMemorySize, 66560);
    prep_k<<<4928, 256, 66560>>>(x, wq, wk, wv, wo, xh, w1h, w2h);

    {   // conv1: IC=256 (8 x 32-ic chunks), OCTOT=192, fp16 transposed output
        auto k = conv_mma<8, 192, true>;
        cudaFuncSetAttribute(k, cudaFuncAttributeMaxDynamicSharedMemorySize,
                             CONV_SMEM);
        k<<<dim3(3, 64, 8), 256, CONV_SMEM>>>(xh, w1h,
                                              qkv, nullptr, nullptr, nullptr);
    }

    cudaFuncSetAttribute(attn_kernel,
                         cudaFuncAttributeMaxDynamicSharedMemorySize, ATTN_SMEM);
    attn_kernel<<<dim3(T_, B_, 2), 256, ATTN_SMEM>>>(qkv, avh);

    {   // conv2: IC=128 (4 x 32-ic chunks), OCTOT=256, fp32 out + residual
        auto k = conv_mma<4, 256, false>;
        cudaFuncSetAttribute(k, cudaFuncAttributeMaxDynamicSharedMemorySize,
                             CONV_SMEM);
        k<<<dim3(4, 64, 8), 256, CONV_SMEM>>>(avh, w2h,
                                              nullptr, out, x, sigma);
    }
}